// round 1
// baseline (speedup 1.0000x reference)
#include <cuda_runtime.h>
#include <cstdint>
#include <math.h>

#define D_MODEL 768
#define D_INNER 768
#define D_STATE 8
#define BATCH 4
#define SEQ 8192
#define NTOK (BATCH*SEQ)          /* 32768 */
#define CHUNK 256
#define NCHUNK (SEQ/CHUNK)        /* 32 */

// -------- scratch (allocation-free: __device__ globals) --------
__device__ float g_XZ[(size_t)NTOK * 2 * D_INNER];   // 192 MB : in_proj output
__device__ float g_T [(size_t)NTOK * D_INNER];       //  96 MB : t = (localcum*BC+u*D)*silz, later fixed up in place
__device__ float g_SZ[(size_t)NTOK * D_INNER];       //  96 MB : silu(z)
__device__ float g_CHS[BATCH * NCHUNK * D_INNER];    // chunk sums
__device__ float g_CBC[BATCH * NCHUNK * D_INNER];    // exclusive-carry * BC

// ================= TF32 GEMM (mma.sync m16n8k8) =================
#define BM 128
#define BN 128
#define BK 16
#define APAD 20    // A smem row stride (floats): bank-conflict-free a-frag loads
#define BPAD 136   // B smem row stride (floats): bank-conflict-free b-frag loads

__device__ __forceinline__ uint32_t f2tf32(float f) {
    uint32_t u;
    asm("cvt.rna.tf32.f32 %0, %1;" : "=r"(u) : "f"(f));
    return u;
}

__device__ __forceinline__ void mma_tf32(float* d, const uint32_t* a, const uint32_t* b) {
    asm volatile(
        "mma.sync.aligned.m16n8k8.row.col.f32.tf32.tf32.f32 "
        "{%0,%1,%2,%3}, {%4,%5,%6,%7}, {%8,%9}, {%0,%1,%2,%3};"
        : "+f"(d[0]), "+f"(d[1]), "+f"(d[2]), "+f"(d[3])
        : "r"(a[0]), "r"(a[1]), "r"(a[2]), "r"(a[3]), "r"(b[0]), "r"(b[1]));
}

__device__ __forceinline__ void cp16(void* smem, const void* g) {
    uint32_t sa = (uint32_t)__cvta_generic_to_shared(smem);
    asm volatile("cp.async.cg.shared.global [%0], [%1], 16;" :: "r"(sa), "l"(g));
}

// asel: 0 -> A = Aext ; 1 -> A = g_T
// csel: 0 -> C = Cext ; 1 -> C = g_XZ
__global__ void __launch_bounds__(256)
gemm_tf32(const float* __restrict__ Aext, const float* __restrict__ Bmat,
          float* __restrict__ Cext, int M, int N, int K, int asel, int csel)
{
    const float* __restrict__ A = asel ? g_T : Aext;
    float* __restrict__ C = csel ? g_XZ : Cext;

    __shared__ __align__(16) float sA[2][BM * APAD];
    __shared__ __align__(16) float sB[2][BK * BPAD];

    const int tid  = threadIdx.x;
    const int warp = tid >> 5;
    const int lane = tid & 31;
    const int warpM = warp >> 2;       // 0..1   (warp tile 64 x 32)
    const int warpN = warp & 3;        // 0..3
    const int gid = lane >> 2;         // 0..7
    const int q   = lane & 3;          // 0..3

    const int bm = blockIdx.y * BM;
    const int bn = blockIdx.x * BN;

    float acc[4][4][4];
    #pragma unroll
    for (int mt = 0; mt < 4; ++mt)
        #pragma unroll
        for (int nt = 0; nt < 4; ++nt)
            #pragma unroll
            for (int i = 0; i < 4; ++i) acc[mt][nt][i] = 0.f;

    const int KT = K / BK;

    // --- async tile load: stage s, k-tile kt ---
    auto load_stage = [&](int s, int kt) {
        #pragma unroll
        for (int it = 0; it < 2; ++it) {
            int idx = it * 256 + tid;           // 0..511
            int ar  = idx >> 2;                 // 0..127
            int ac4 = idx & 3;                  // 0..3
            cp16(&sA[s][ar * APAD + ac4 * 4],
                 A + (size_t)(bm + ar) * K + kt * BK + ac4 * 4);
            int br  = idx >> 5;                 // 0..15
            int bc4 = idx & 31;                 // 0..31
            cp16(&sB[s][br * BPAD + bc4 * 4],
                 Bmat + (size_t)(kt * BK + br) * N + bn + bc4 * 4);
        }
    };

    load_stage(0, 0);
    asm volatile("cp.async.commit_group;");

    for (int kt = 0; kt < KT; ++kt) {
        asm volatile("cp.async.wait_group 0;");
        __syncthreads();
        if (kt + 1 < KT) {
            load_stage((kt + 1) & 1, kt + 1);
            asm volatile("cp.async.commit_group;");
        }
        const float* __restrict__ sAp = sA[kt & 1];
        const float* __restrict__ sBp = sB[kt & 1];

        #pragma unroll
        for (int k8 = 0; k8 < BK / 8; ++k8) {
            uint32_t af[4][4], bf[4][2];
            #pragma unroll
            for (int mt = 0; mt < 4; ++mt) {
                int r0 = warpM * 64 + mt * 16 + gid;
                af[mt][0] = f2tf32(sAp[(r0    ) * APAD + k8 * 8 + q    ]);
                af[mt][1] = f2tf32(sAp[(r0 + 8) * APAD + k8 * 8 + q    ]);
                af[mt][2] = f2tf32(sAp[(r0    ) * APAD + k8 * 8 + q + 4]);
                af[mt][3] = f2tf32(sAp[(r0 + 8) * APAD + k8 * 8 + q + 4]);
            }
            #pragma unroll
            for (int nt = 0; nt < 4; ++nt) {
                int cn = warpN * 32 + nt * 8 + gid;
                bf[nt][0] = f2tf32(sBp[(k8 * 8 + q    ) * BPAD + cn]);
                bf[nt][1] = f2tf32(sBp[(k8 * 8 + q + 4) * BPAD + cn]);
            }
            #pragma unroll
            for (int mt = 0; mt < 4; ++mt)
                #pragma unroll
                for (int nt = 0; nt < 4; ++nt)
                    mma_tf32(acc[mt][nt], af[mt], bf[nt]);
        }
    }

    // epilogue
    #pragma unroll
    for (int mt = 0; mt < 4; ++mt) {
        int gm = bm + warpM * 64 + mt * 16 + gid;
        #pragma unroll
        for (int nt = 0; nt < 4; ++nt) {
            int gn = bn + warpN * 32 + nt * 8 + q * 2;
            float2 v0 = make_float2(acc[mt][nt][0], acc[mt][nt][1]);
            float2 v1 = make_float2(acc[mt][nt][2], acc[mt][nt][3]);
            *(float2*)&C[(size_t)gm * N + gn]       = v0;
            *(float2*)&C[(size_t)(gm + 8) * N + gn] = v1;
        }
    }
}

// ============ Phase A: conv3 + silu + local cumsum per chunk ============
// grid (D_INNER/256, NCHUNK, BATCH), block 256. Thread = one channel, one chunk.
__global__ void __launch_bounds__(256)
scan_kernel(const float* __restrict__ conv_w, const float* __restrict__ conv_b,
            const float* __restrict__ Bm, const float* __restrict__ Cm,
            const float* __restrict__ Dv)
{
    const int d = blockIdx.x * 256 + threadIdx.x;
    const int c = blockIdx.y;
    const int b = blockIdx.z;

    const float w0 = conv_w[d * 3 + 0];
    const float w1 = conv_w[d * 3 + 1];
    const float w2 = conv_w[d * 3 + 2];
    const float cb = conv_b[d];
    float bc = 0.f;
    #pragma unroll
    for (int s = 0; s < D_STATE; ++s) bc += Bm[d * D_STATE + s] * Cm[d * D_STATE + s];
    const float Dd = Dv[d];

    const int l0 = c * CHUNK;
    size_t base  = ((size_t)(b * SEQ + l0)) * (2 * D_INNER) + d;
    size_t obase = ((size_t)(b * SEQ + l0)) * D_INNER + d;

    float xm1 = (l0 >= 1) ? g_XZ[base - 1 * 2 * D_INNER] : 0.f;
    float xm2 = (l0 >= 2) ? g_XZ[base - 2 * 2 * D_INNER] : 0.f;

    float run = 0.f;
    for (int i = 0; i < CHUNK; ++i) {
        float x0 = g_XZ[base];
        float zv = g_XZ[base + D_INNER];
        float pre = fmaf(w0, xm2, fmaf(w1, xm1, fmaf(w2, x0, cb)));
        float u  = pre / (1.f + expf(-pre));
        run += u;
        float sz = zv / (1.f + expf(-zv));
        g_T[obase]  = (run * bc + u * Dd) * sz;
        g_SZ[obase] = sz;
        xm2 = xm1; xm1 = x0;
        base  += 2 * D_INNER;
        obase += D_INNER;
    }
    g_CHS[(b * NCHUNK + c) * D_INNER + d] = run;
}

// ============ Phase B: exclusive scan of chunk sums, pre-mult by BC ============
__global__ void carry_kernel(const float* __restrict__ Bm, const float* __restrict__ Cm)
{
    int idx = blockIdx.x * blockDim.x + threadIdx.x;   // BATCH*D_INNER = 3072
    if (idx >= BATCH * D_INNER) return;
    int b = idx / D_INNER, d = idx % D_INNER;
    float bc = 0.f;
    #pragma unroll
    for (int s = 0; s < D_STATE; ++s) bc += Bm[d * D_STATE + s] * Cm[d * D_STATE + s];
    float car = 0.f;
    for (int c = 0; c < NCHUNK; ++c) {
        g_CBC[(b * NCHUNK + c) * D_INNER + d] = car * bc;
        car += g_CHS[(b * NCHUNK + c) * D_INNER + d];
    }
}

// ============ Phase C: t += carryBC * silz  (in place, float4) ============
__global__ void __launch_bounds__(256)
fix_kernel()
{
    int i = blockIdx.x * 256 + threadIdx.x;      // NTOK * 192 threads
    int m  = i / (D_INNER / 4);
    int d4 = i % (D_INNER / 4);
    int l = m & (SEQ - 1);
    int b = m >> 13;
    int c = l >> 8;                               // CHUNK=256
    float4 t  = ((float4*)g_T )[(size_t)m * (D_INNER / 4) + d4];
    float4 sz = ((float4*)g_SZ)[(size_t)m * (D_INNER / 4) + d4];
    float4 cb = ((const float4*)g_CBC)[(size_t)(b * NCHUNK + c) * (D_INNER / 4) + d4];
    t.x = fmaf(cb.x, sz.x, t.x);
    t.y = fmaf(cb.y, sz.y, t.y);
    t.z = fmaf(cb.z, sz.z, t.z);
    t.w = fmaf(cb.w, sz.w, t.w);
    ((float4*)g_T)[(size_t)m * (D_INNER / 4) + d4] = t;
}

// ============================ launch ============================
extern "C" void kernel_launch(void* const* d_in, const int* in_sizes, int n_in,
                              void* d_out, int out_size)
{
    const float* x      = (const float*)d_in[0];
    const float* W_in   = (const float*)d_in[1];
    const float* conv_w = (const float*)d_in[2];
    const float* conv_b = (const float*)d_in[3];
    const float* Bm     = (const float*)d_in[4];
    const float* Cm     = (const float*)d_in[5];
    const float* Dv     = (const float*)d_in[6];
    const float* W_out  = (const float*)d_in[7];
    float* out = (float*)d_out;

    // GEMM1: XZ = X @ W_in   [32768,768] x [768,1536]
    dim3 g1((2 * D_INNER) / BN, NTOK / BM);
    gemm_tf32<<<g1, 256>>>(x, W_in, nullptr, NTOK, 2 * D_INNER, D_MODEL, 0, 1);

    // conv + silu + chunked scan
    scan_kernel<<<dim3(D_INNER / 256, NCHUNK, BATCH), 256>>>(conv_w, conv_b, Bm, Cm, Dv);
    carry_kernel<<<(BATCH * D_INNER + 255) / 256, 256>>>(Bm, Cm);
    fix_kernel<<<(NTOK * (D_INNER / 4)) / 256, 256>>>();

    // GEMM2: out = T @ W_out   [32768,768] x [768,768]
    dim3 g2(D_MODEL / BN, NTOK / BM);
    gemm_tf32<<<g2, 256>>>(nullptr, W_out, out, NTOK, D_MODEL, D_MODEL, 1, 0);
}